// round 2
// baseline (speedup 1.0000x reference)
#include <cuda_runtime.h>
#include <math.h>

#define NSEG   2047
#define NPIX   16384
#define GRID_N 128
#define CH     32          // segments per chunk
#define NCHUNK 64          // 64*32 = 2048 >= 2047
#define NBAND  8           // 8 bands of 16 rows
#define PPT    16          // pixels (columns) per thread
#define GAMMA_F 200.0f

typedef unsigned long long u64;

// Per-segment SoA (packed duplicated float2 where consumed as f32x2)
__device__ float2 g_npjx [2][NSEG];   // (-pjx, -pjx)
__device__ float2 g_nvx2 [2][NSEG];   // (-2vx, -2vx)
__device__ float2 g_vn   [2][NSEG];   // (|v|^2, |v|^2)
__device__ float  g_pjy  [2][NSEG];
__device__ float  g_nvy2 [2][NSEG];   // -2vy
__device__ float  g_ninvh[2][NSEG];   // -0.5/|v|^2 (0 if degenerate/masked)

__device__ unsigned g_min[2][NPIX];   // min d^2 as uint bits (d2>=0)

// ---- f32x2 helpers (sm_103a packed fp32 pipe) --------------------------------
__device__ __forceinline__ u64 pk2(float lo, float hi) {
    u64 r; asm("mov.b64 %0,{%1,%2};" : "=l"(r) : "f"(lo), "f"(hi)); return r;
}
__device__ __forceinline__ void upk2(float& lo, float& hi, u64 v) {
    asm("mov.b64 {%0,%1},%2;" : "=f"(lo), "=f"(hi) : "l"(v));
}
__device__ __forceinline__ u64 f2add(u64 a, u64 b) {
    u64 r; asm("add.rn.f32x2 %0,%1,%2;" : "=l"(r) : "l"(a), "l"(b)); return r;
}
__device__ __forceinline__ u64 f2fma(u64 a, u64 b, u64 c) {
    u64 r; asm("fma.rn.f32x2 %0,%1,%2,%3;" : "=l"(r) : "l"(a), "l"(b), "l"(c)); return r;
}
__device__ __forceinline__ float satmul(float a, float b) {
    float r; asm("mul.rn.sat.f32 %0,%1,%2;" : "=f"(r) : "f"(a), "f"(b)); return r;
}

// ---------------------------------------------------------------------------
// prep: per-segment constants + init g_min to +inf + zero out scalar.
// grid = (16, 2), block = 128  -> 4096 threads, 8 g_min words each.
// ---------------------------------------------------------------------------
__global__ void prep_kernel(const float* __restrict__ pred,
                            const float* __restrict__ gt,
                            float* __restrict__ out) {
    const int flat = (blockIdx.y * gridDim.x + blockIdx.x) * blockDim.x + threadIdx.x;
#pragma unroll
    for (int k = 0; k < 8; k++)
        ((unsigned*)g_min)[flat * 8 + k] = 0x7F800000u;   // +inf
    if (flat == 0) out[0] = 0.0f;

    const int s = blockIdx.x * blockDim.x + threadIdx.x;
    const int w = blockIdx.y;
    if (s >= NSEG) return;
    const float* c = w ? gt : pred;

    const float pen = c[s * 3 + 2];
    const bool masked = w ? (pen != 0.0f) : (pen > 0.5f);

    float npjx, pjy, nvx2, nvy2, vn, ninvh;
    if (masked) {
        npjx = -1e18f; pjy = 1e18f;
        nvx2 = 0.0f; nvy2 = 0.0f; vn = 0.0f; ninvh = 0.0f;
    } else {
        const float pix = (c[s * 3 + 0]       - 0.5f) * 2.0f;
        const float piy = (c[s * 3 + 1]       - 0.5f) * 2.0f;
        const float pjx = (c[(s + 1) * 3 + 0] - 0.5f) * 2.0f;
        const float pjyv= (c[(s + 1) * 3 + 1] - 0.5f) * 2.0f;
        const float vx = pix - pjx;
        const float vy = piy - pjyv;
        vn = vx * vx + vy * vy;
        npjx = -pjx; pjy = pjyv;
        nvx2 = -2.0f * vx; nvy2 = -2.0f * vy;
        ninvh = (vn == 0.0f) ? 0.0f : (-0.5f / vn);
    }
    g_npjx [w][s] = make_float2(npjx, npjx);
    g_nvx2 [w][s] = make_float2(nvx2, nvx2);
    g_vn   [w][s] = make_float2(vn, vn);
    g_pjy  [w][s] = pjy;
    g_nvy2 [w][s] = nvy2;
    g_ninvh[w][s] = ninvh;
}

// ---------------------------------------------------------------------------
// main: grid = (NBAND, NCHUNK, 2), block = 128.
// Thread owns 16 contiguous columns of one row (8 f32x2 pixel pairs).
// d^2 = u^2 + t*(t*vn - 2uv), t = sat(uv/vn) computed via negated constants:
//   M2uv = fma(ux, -2vx, uy*(-2vy));  t = sat(M2uv * (-0.5/vn));
//   d2   = fma(t, fma(t, vn, M2uv), u2)
// 5 packed fma-pipe ops + 2 scalar sat-muls per pixel pair (3.5 fma/px).
// ---------------------------------------------------------------------------
__global__ void __launch_bounds__(128) main_kernel() {
    const int w     = blockIdx.z;
    const int band  = blockIdx.x;
    const int chunk = blockIdx.y;

    __shared__ u64  s_npjx[CH], s_nvx2[CH], s_vn[CH];
    __shared__ float s_pjy[CH], s_nvy2[CH], s_ninvh[CH];

    const int s0  = chunk * CH;
    const int cnt = (s0 + CH <= NSEG) ? CH : (NSEG - s0);
    if ((int)threadIdx.x < cnt) {
        const int s = s0 + threadIdx.x;
        s_npjx [threadIdx.x] = ((const u64*)g_npjx[w])[s];
        s_nvx2 [threadIdx.x] = ((const u64*)g_nvx2[w])[s];
        s_vn   [threadIdx.x] = ((const u64*)g_vn  [w])[s];
        s_pjy  [threadIdx.x] = g_pjy  [w][s];
        s_nvy2 [threadIdx.x] = g_nvy2 [w][s];
        s_ninvh[threadIdx.x] = g_ninvh[w][s];
    }
    __syncthreads();

    const int t   = threadIdx.x;
    const int r   = t >> 3;                 // 0..15 row within band
    const int c0  = (t & 7) * PPT;          // 0..112 first column
    const int row = band * 16 + r;
    const float step = 2.0f / 127.0f;
    const float gy = fmaf((float)row, step, -1.0f);

    u64 gxp[8];
    float m[16];
#pragma unroll
    for (int k = 0; k < 8; k++) {
        const float a = fmaf((float)(c0 + 2 * k    ), step, -1.0f);
        const float b = fmaf((float)(c0 + 2 * k + 1), step, -1.0f);
        gxp[k] = pk2(a, b);
        m[2 * k]     = __int_as_float(0x7F800000);
        m[2 * k + 1] = __int_as_float(0x7F800000);
    }

#pragma unroll 1
    for (int i = 0; i < cnt; i++) {
        const u64 npjxp = s_npjx[i];
        const u64 nvx2p = s_nvx2[i];
        const u64 vnp   = s_vn[i];
        const float pjy   = s_pjy[i];
        const float nvy2  = s_nvy2[i];
        const float ninvh = s_ninvh[i];

        const float uy   = gy - pjy;
        const float uy2s = uy * uy;
        const float ncys = uy * nvy2;
        const u64 uy2p = pk2(uy2s, uy2s);
        const u64 ncyp = pk2(ncys, ncys);

#pragma unroll
        for (int k = 0; k < 8; k++) {
            const u64 uxp  = f2add(gxp[k], npjxp);            // u.x
            const u64 m2uv = f2fma(uxp, nvx2p, ncyp);         // -2*dot(u,v)
            const u64 u2p  = f2fma(uxp, uxp, uy2p);           // |u|^2
            float mlo, mhi; upk2(mlo, mhi, m2uv);
            const float tlo = satmul(mlo, ninvh);             // clamp01(uv/vn)
            const float thi = satmul(mhi, ninvh);
            const u64 tp    = pk2(tlo, thi);
            const u64 innr  = f2fma(tp, vnp, m2uv);           // t*vn - 2uv
            const u64 d2p   = f2fma(tp, innr, u2p);           // d^2
            float dlo, dhi; upk2(dlo, dhi, d2p);
            m[2 * k]     = fminf(m[2 * k],     dlo);
            m[2 * k + 1] = fminf(m[2 * k + 1], dhi);
        }
    }

    unsigned* dst = g_min[w] + row * GRID_N + c0;
#pragma unroll
    for (int k = 0; k < 16; k++)
        atomicMin(dst + k, __float_as_uint(m[k]));
}

// ---------------------------------------------------------------------------
// reduce: beta = exp(-gamma*min_d2), MSE. grid = 64, block = 256.
// ---------------------------------------------------------------------------
__global__ void reduce_kernel(float* __restrict__ out) {
    const int p = blockIdx.x * 256 + threadIdx.x;
    const float ep = __expf(-GAMMA_F * __uint_as_float(g_min[0][p]));
    const float eg = __expf(-GAMMA_F * __uint_as_float(g_min[1][p]));
    const float d  = ep - eg;
    float v = d * d;

#pragma unroll
    for (int o = 16; o > 0; o >>= 1)
        v += __shfl_down_sync(0xFFFFFFFFu, v, o);

    __shared__ float ws[8];
    const int lane = threadIdx.x & 31;
    const int wid  = threadIdx.x >> 5;
    if (lane == 0) ws[wid] = v;
    __syncthreads();
    if (wid == 0) {
        float bv = (lane < 8) ? ws[lane] : 0.0f;
#pragma unroll
        for (int o = 4; o > 0; o >>= 1)
            bv += __shfl_down_sync(0xFFFFFFFFu, bv, o);
        if (lane == 0)
            atomicAdd(out, bv * (1.0f / (float)NPIX));
    }
}

// ---------------------------------------------------------------------------
extern "C" void kernel_launch(void* const* d_in, const int* in_sizes, int n_in,
                              void* d_out, int out_size) {
    const float* pred = (const float*)d_in[0];
    const float* gt   = (const float*)d_in[1];
    float* out = (float*)d_out;

    dim3 pgrid((NSEG + 127) / 128, 2, 1);
    prep_kernel<<<pgrid, 128>>>(pred, gt, out);

    dim3 mgrid(NBAND, NCHUNK, 2);
    main_kernel<<<mgrid, 128>>>();

    reduce_kernel<<<NPIX / 256, 256>>>(out);
}

// round 3
// speedup vs baseline: 1.3532x; 1.3532x over previous
#include <cuda_runtime.h>
#include <math.h>

#define NSEG    2047
#define NPIX    16384
#define GAMMA_F 200.0f
#define STEPF   (2.0f / 127.0f)
// 2 * tile half-diagonal (tile = 8x8 px, center at +3.5 px each axis)
// 2r = 7 * sqrt(2) * STEP; + 1e-3 safety margin for fp roundoff in the bound
#define THR_ADD (9.899495f * STEPF + 1e-3f)
#define FINF    __int_as_float(0x7F800000)

__device__ __forceinline__ float satmul(float a, float b) {
    float r; asm("mul.rn.sat.f32 %0,%1,%2;" : "=f"(r) : "f"(a), "f"(b)); return r;
}

__global__ void zero_kernel(float* out) {
    if (threadIdx.x == 0) out[0] = 0.0f;
}

// One CTA per 8x8-pixel tile. 128 threads.
// Phase 1: all threads brute-force both transforms' 2047 segments at the TILE
//          CENTER, block-min -> U, then cull: keep segment iff
//          d2(center) < (sqrt(U) + 2r + eps)^2.  Exact by triangle inequality.
// Phase 2: chunk candidate constants through smem; thread = (pixel p = tid&63,
//          half h = tid>>6) evaluates every other list entry for its pixel,
//          for BOTH transforms.
// Phase 3: merge halves, beta = expf(-gamma*min d2), MSE partial -> atomicAdd.
__global__ void __launch_bounds__(128) tile_kernel(const float* __restrict__ pred,
                                                   const float* __restrict__ gt,
                                                   float* __restrict__ out) {
    const int tid  = threadIdx.x;
    const int tile = blockIdx.x;
    const int tx = tile & 15, ty = tile >> 4;

    const float cx = fmaf((float)(tx * 8) + 3.5f, STEPF, -1.0f);
    const float cy = fmaf((float)(ty * 8) + 3.5f, STEPF, -1.0f);

    __shared__ unsigned short s_list[2][2048];
    __shared__ float s_pjx[256], s_pjy[256], s_vx[256], s_vy[256], s_inv[256];
    __shared__ float s_m[2][64];
    __shared__ float s_red[4];
    __shared__ int   s_cnt[2];

    if (tid < 2) s_cnt[tid] = 0;

    // ---------------- Phase 1: center eval + cull ----------------
    for (int w = 0; w < 2; ++w) {
        const float* __restrict__ c = w ? gt : pred;
        float d2c[16];
        float lmin = FINF;
#pragma unroll
        for (int k = 0; k < 16; ++k) {
            const int s = tid + (k << 7);
            float d2 = FINF;
            if (s < NSEG) {
                const float pen = __ldg(&c[s * 3 + 2]);
                const bool masked = w ? (pen != 0.0f) : (pen > 0.5f);
                if (!masked) {
                    const float pjx = fmaf(__ldg(&c[s * 3 + 3]), 2.0f, -1.0f);
                    const float pjy = fmaf(__ldg(&c[s * 3 + 4]), 2.0f, -1.0f);
                    const float vx  = fmaf(__ldg(&c[s * 3 + 0]), 2.0f, -1.0f) - pjx;
                    const float vy  = fmaf(__ldg(&c[s * 3 + 1]), 2.0f, -1.0f) - pjy;
                    const float vn  = vx * vx + vy * vy;
                    const float inv = (vn == 0.0f) ? 0.0f : (1.0f / vn);
                    const float ux = cx - pjx, uy = cy - pjy;
                    const float uv = fmaf(ux, vx, uy * vy);
                    const float t  = satmul(uv, inv);
                    const float dx = fmaf(-t, vx, ux);
                    const float dy = fmaf(-t, vy, uy);
                    d2 = fmaf(dy, dy, dx * dx);
                }
            }
            d2c[k] = d2;
            lmin = fminf(lmin, d2);
        }
#pragma unroll
        for (int o = 16; o > 0; o >>= 1)
            lmin = fminf(lmin, __shfl_xor_sync(0xFFFFFFFFu, lmin, o));
        if ((tid & 31) == 0) s_red[tid >> 5] = lmin;
        __syncthreads();
        const float U   = fminf(fminf(s_red[0], s_red[1]), fminf(s_red[2], s_red[3]));
        const float thd = sqrtf(U) + THR_ADD;
        const float thr = thd * thd;   // U=inf (all masked) -> thr=inf; INF < INF is false
#pragma unroll
        for (int k = 0; k < 16; ++k) {
            const int s = tid + (k << 7);
            if (s < NSEG && d2c[k] < thr) {
                const int pos = atomicAdd(&s_cnt[w], 1);
                s_list[w][pos] = (unsigned short)s;
            }
        }
        __syncthreads();
    }

    // ---------------- Phase 2: per-pixel min over candidates ----------------
    const int p = tid & 63, h = tid >> 6;
    const int row = p >> 3, col = p & 7;
    const float gx = fmaf((float)(tx * 8 + col), STEPF, -1.0f);
    const float gy = fmaf((float)(ty * 8 + row), STEPF, -1.0f);

    float m[2] = {FINF, FINF};
    for (int w = 0; w < 2; ++w) {
        const float* __restrict__ c = w ? gt : pred;
        const int len = s_cnt[w];
        for (int off = 0; off < len; off += 256) {
            const int cn = min(256, len - off);
            for (int j = tid; j < cn; j += 128) {
                const int s = s_list[w][off + j];
                const float pjx = fmaf(__ldg(&c[s * 3 + 3]), 2.0f, -1.0f);
                const float pjy = fmaf(__ldg(&c[s * 3 + 4]), 2.0f, -1.0f);
                const float vx  = fmaf(__ldg(&c[s * 3 + 0]), 2.0f, -1.0f) - pjx;
                const float vy  = fmaf(__ldg(&c[s * 3 + 1]), 2.0f, -1.0f) - pjy;
                const float vn  = vx * vx + vy * vy;
                s_pjx[j] = pjx; s_pjy[j] = pjy;
                s_vx[j]  = vx;  s_vy[j]  = vy;
                s_inv[j] = (vn == 0.0f) ? 0.0f : (1.0f / vn);
            }
            __syncthreads();
            float mm = m[w];
#pragma unroll 2
            for (int j = h; j < cn; j += 2) {
                const float pjx = s_pjx[j], pjy = s_pjy[j];
                const float vx = s_vx[j], vy = s_vy[j], inv = s_inv[j];
                const float ux = gx - pjx, uy = gy - pjy;
                const float uv = fmaf(ux, vx, uy * vy);
                const float t  = satmul(uv, inv);
                const float dx = fmaf(-t, vx, ux);
                const float dy = fmaf(-t, vy, uy);
                mm = fminf(mm, fmaf(dy, dy, dx * dx));
            }
            m[w] = mm;
            __syncthreads();
        }
    }

    // ---------------- Phase 3: merge halves + loss ----------------
    if (h == 1) { s_m[0][p] = m[0]; s_m[1][p] = m[1]; }
    __syncthreads();
    float v = 0.0f;
    if (h == 0) {
        const float q0 = fminf(m[0], s_m[0][p]);
        const float q1 = fminf(m[1], s_m[1][p]);
        const float bp = expf(-GAMMA_F * q0);
        const float bg = expf(-GAMMA_F * q1);
        const float d  = bp - bg;
        v = d * d;
    }
#pragma unroll
    for (int o = 16; o > 0; o >>= 1)
        v += __shfl_xor_sync(0xFFFFFFFFu, v, o);
    if ((tid & 31) == 0) s_red[tid >> 5] = v;
    __syncthreads();
    if (tid == 0)
        atomicAdd(out, (s_red[0] + s_red[1] + s_red[2] + s_red[3]) * (1.0f / (float)NPIX));
}

extern "C" void kernel_launch(void* const* d_in, const int* in_sizes, int n_in,
                              void* d_out, int out_size) {
    const float* pred = (const float*)d_in[0];
    const float* gt   = (const float*)d_in[1];
    float* out = (float*)d_out;

    zero_kernel<<<1, 32>>>(out);
    tile_kernel<<<256, 128>>>(pred, gt, out);
}

// round 4
// speedup vs baseline: 2.1619x; 1.5977x over previous
#include <cuda_runtime.h>
#include <math.h>

#define NSEG    2047
#define NPIX    16384
#define GAMMA_F 200.0f
#define STEPF   (2.0f / 127.0f)
// 2 * tile half-diagonal (tile = 8x8 px): 2 * 3.5*sqrt(2) px = 9.8995 px
#define THR_ADD (9.899495f * STEPF + 1e-3f)
#define FINF    __int_as_float(0x7F800000)

__device__ __forceinline__ float satmul(float a, float b) {
    float r; asm("mul.rn.sat.f32 %0,%1,%2;" : "=f"(r) : "f"(a), "f"(b)); return r;
}

// Per-segment SoA: (pjx, pjy, vx, vy) + 1/|v|^2. Masked: pj=1e9, v=0, inv=0.
__device__ float4 g_seg[2][2048];
__device__ float  g_inv[2][2048];
__device__ float  g_min[2][NPIX];    // per-pixel min d^2

// ---------------------------------------------------------------------------
// prep: coordinate conversion + segment constants, once. grid (8,2) x 256.
// ---------------------------------------------------------------------------
__global__ void prep_kernel(const float* __restrict__ pred,
                            const float* __restrict__ gt,
                            float* __restrict__ out) {
    const int s = blockIdx.x * 256 + threadIdx.x;
    const int w = blockIdx.y;
    if (s == 0 && w == 0) out[0] = 0.0f;
    if (s >= NSEG) return;
    const float* __restrict__ c = w ? gt : pred;

    const float pen = c[s * 3 + 2];
    const bool masked = w ? (pen != 0.0f) : (pen > 0.5f);

    float4 q; float inv;
    if (masked) {
        q = make_float4(1e9f, 1e9f, 0.0f, 0.0f);
        inv = 0.0f;
    } else {
        const float pjx = fmaf(c[s * 3 + 3], 2.0f, -1.0f);
        const float pjy = fmaf(c[s * 3 + 4], 2.0f, -1.0f);
        const float vx  = fmaf(c[s * 3 + 0], 2.0f, -1.0f) - pjx;
        const float vy  = fmaf(c[s * 3 + 1], 2.0f, -1.0f) - pjy;
        const float vn  = vx * vx + vy * vy;
        q = make_float4(pjx, pjy, vx, vy);
        inv = (vn == 0.0f) ? 0.0f : (1.0f / vn);
    }
    g_seg[w][s] = q;
    g_inv[w][s] = inv;
}

// ---------------------------------------------------------------------------
// tile: grid (256 tiles, 2 transforms), block 128. One 8x8-px tile per CTA.
// Phase 1: 16 segs/thread evaluated at tile center -> block-min U -> cull
//          keep d(s,c) < sqrt(U) + 2r + eps   (exact via triangle inequality)
// Phase 2: candidates staged in smem; thread = (pixel p = tid&63, half h);
//          two independent min accumulators for ILP.
// Phase 3: merge halves, store per-pixel min (exclusive ownership, no atomics)
// ---------------------------------------------------------------------------
__global__ void __launch_bounds__(128) tile_kernel() {
    const int tid = threadIdx.x;
    const int w   = blockIdx.y;
    const int tx  = blockIdx.x & 15, ty = blockIdx.x >> 4;

    const float cx = fmaf((float)(tx * 8) + 3.5f, STEPF, -1.0f);
    const float cy = fmaf((float)(ty * 8) + 3.5f, STEPF, -1.0f);

    __shared__ unsigned short s_list[2048];
    __shared__ float4 s_seg[256];
    __shared__ float  s_inv[256];
    __shared__ float  s_m[64];
    __shared__ float  s_red[4];
    __shared__ int    s_cnt;

    if (tid == 0) s_cnt = 0;

    const float4* __restrict__ segA = g_seg[w];
    const float*  __restrict__ invA = g_inv[w];

    // ---------------- Phase 1 ----------------
    float d2c[16];
    float lmin = FINF;
#pragma unroll
    for (int k = 0; k < 16; ++k) {
        const int s = tid + (k << 7);
        float d2 = FINF;
        if (s < NSEG) {
            const float4 q  = segA[s];
            const float inv = invA[s];
            const float ux = cx - q.x, uy = cy - q.y;
            const float uv = fmaf(ux, q.z, uy * q.w);
            const float t  = satmul(uv, inv);
            const float dx = fmaf(-t, q.z, ux);
            const float dy = fmaf(-t, q.w, uy);
            d2 = fmaf(dy, dy, dx * dx);
        }
        d2c[k] = d2;
        lmin = fminf(lmin, d2);
    }
#pragma unroll
    for (int o = 16; o > 0; o >>= 1)
        lmin = fminf(lmin, __shfl_xor_sync(0xFFFFFFFFu, lmin, o));
    if ((tid & 31) == 0) s_red[tid >> 5] = lmin;
    __syncthreads();
    const float U   = fminf(fminf(s_red[0], s_red[1]), fminf(s_red[2], s_red[3]));
    const float thd = sqrtf(U) + THR_ADD;
    const float thr = thd * thd;
#pragma unroll
    for (int k = 0; k < 16; ++k) {
        const int s = tid + (k << 7);
        if (s < NSEG && d2c[k] < thr) {
            const int pos = atomicAdd(&s_cnt, 1);
            s_list[pos] = (unsigned short)s;
        }
    }
    __syncthreads();

    // ---------------- Phase 2 ----------------
    const int p = tid & 63, h = tid >> 6;
    const int row = p >> 3, col = p & 7;
    const float gx = fmaf((float)(tx * 8 + col), STEPF, -1.0f);
    const float gy = fmaf((float)(ty * 8 + row), STEPF, -1.0f);

    float m0 = FINF, m1 = FINF;
    const int len = s_cnt;
    for (int off = 0; off < len; off += 256) {
        const int cn = min(256, len - off);
        for (int j = tid; j < cn; j += 128) {
            const int s = s_list[off + j];
            s_seg[j] = segA[s];
            s_inv[j] = invA[s];
        }
        __syncthreads();
        // two independent accumulator chains: j = h, h+2, h+4, ...
        int j = h;
        for (; j + 2 < cn; j += 4) {
            {
                const float4 q = s_seg[j]; const float inv = s_inv[j];
                const float ux = gx - q.x, uy = gy - q.y;
                const float uv = fmaf(ux, q.z, uy * q.w);
                const float t  = satmul(uv, inv);
                const float dx = fmaf(-t, q.z, ux);
                const float dy = fmaf(-t, q.w, uy);
                m0 = fminf(m0, fmaf(dy, dy, dx * dx));
            }
            {
                const float4 q = s_seg[j + 2]; const float inv = s_inv[j + 2];
                const float ux = gx - q.x, uy = gy - q.y;
                const float uv = fmaf(ux, q.z, uy * q.w);
                const float t  = satmul(uv, inv);
                const float dx = fmaf(-t, q.z, ux);
                const float dy = fmaf(-t, q.w, uy);
                m1 = fminf(m1, fmaf(dy, dy, dx * dx));
            }
        }
        for (; j < cn; j += 2) {
            const float4 q = s_seg[j]; const float inv = s_inv[j];
            const float ux = gx - q.x, uy = gy - q.y;
            const float uv = fmaf(ux, q.z, uy * q.w);
            const float t  = satmul(uv, inv);
            const float dx = fmaf(-t, q.z, ux);
            const float dy = fmaf(-t, q.w, uy);
            m0 = fminf(m0, fmaf(dy, dy, dx * dx));
        }
        __syncthreads();
    }
    const float m = fminf(m0, m1);

    // ---------------- Phase 3: merge halves, store ----------------
    if (h == 1) s_m[p] = m;
    __syncthreads();
    if (h == 0) {
        const int pix = (ty * 8 + row) * 128 + tx * 8 + col;
        g_min[w][pix] = fminf(m, s_m[p]);
    }
}

// ---------------------------------------------------------------------------
// reduce: beta = exp(-gamma*d2), MSE. grid 64 x 256.
// ---------------------------------------------------------------------------
__global__ void reduce_kernel(float* __restrict__ out) {
    const int p = blockIdx.x * 256 + threadIdx.x;
    const float bp = expf(-GAMMA_F * g_min[0][p]);
    const float bg = expf(-GAMMA_F * g_min[1][p]);
    const float d  = bp - bg;
    float v = d * d;

#pragma unroll
    for (int o = 16; o > 0; o >>= 1)
        v += __shfl_xor_sync(0xFFFFFFFFu, v, o);

    __shared__ float ws[8];
    const int lane = threadIdx.x & 31;
    const int wid  = threadIdx.x >> 5;
    if (lane == 0) ws[wid] = v;
    __syncthreads();
    if (wid == 0) {
        float bv = (lane < 8) ? ws[lane] : 0.0f;
#pragma unroll
        for (int o = 4; o > 0; o >>= 1)
            bv += __shfl_xor_sync(0xFFFFFFFFu, bv, o);
        if (lane == 0)
            atomicAdd(out, bv * (1.0f / (float)NPIX));
    }
}

// ---------------------------------------------------------------------------
extern "C" void kernel_launch(void* const* d_in, const int* in_sizes, int n_in,
                              void* d_out, int out_size) {
    const float* pred = (const float*)d_in[0];
    const float* gt   = (const float*)d_in[1];
    float* out = (float*)d_out;

    dim3 pgrid(8, 2);
    prep_kernel<<<pgrid, 256>>>(pred, gt, out);

    dim3 tgrid(256, 2);
    tile_kernel<<<tgrid, 128>>>();

    reduce_kernel<<<64, 256>>>(out);
}